// round 12
// baseline (speedup 1.0000x reference)
#include <cuda_runtime.h>
#include <cuda_fp16.h>
#include <math.h>
#include <stdint.h>

#define T_TOK 4096
#define DIM   1024
#define HID   512
#define NE    8
#define NSH   2
#define NSLOT (2 * T_TOK)

// offsets (halves) inside g_wt scratch; weights stored TRANSPOSED [n][k] fp16
#define OFF_X   0
#define OFF_W1  4194304
#define OFF_W3  8388608
#define OFF_W2  12582912
#define OFF_SW1 16777216
#define OFF_SW3 17825792
#define OFF_SW2 18874368
#define WT_TOTAL 19922944   // halves (38 MB)

// ---------------- scratch (device globals; no runtime allocation) ----------
// pointer role table: 0=x 1=router_w 2=router_b 3=w1 4=w3 5=w2 6=sw1 7=sw3 8=sw2
__device__ const float* g_ptr[9];

__device__ __align__(16) __half g_wt[WT_TOTAL];
__device__ __align__(16) float  g_gates[T_TOK * 2];
__device__ __align__(16) int    g_eidx[T_TOK * 2];
__device__ __align__(16) int    g_pos[T_TOK * 2];
__device__ __align__(16) int    g_counts[NE];
__device__ __align__(16) int    g_base[NE];
__device__ __align__(16) int    g_tok[NSLOT];
__device__ __align__(16) float  g_slotgate[NSLOT];
__device__ __align__(16) __half g_h[(size_t)NSLOT * HID];        // 8 MB fp16
__device__ __align__(16) float  g_y[(size_t)NSLOT * DIM];        // 32 MB
__device__ __align__(16) __half g_hsh[(size_t)NSH * T_TOK * HID];// 8 MB fp16

// ---------------- helpers ---------------------------------------------------
__device__ __forceinline__ void mma_f16(float c[4],
                                        uint32_t a0, uint32_t a1, uint32_t a2, uint32_t a3,
                                        uint32_t b0, uint32_t b1) {
    asm volatile(
        "mma.sync.aligned.m16n8k16.row.col.f32.f16.f16.f32 "
        "{%0,%1,%2,%3},{%4,%5,%6,%7},{%8,%9},{%0,%1,%2,%3};"
        : "+f"(c[0]), "+f"(c[1]), "+f"(c[2]), "+f"(c[3])
        : "r"(a0), "r"(a1), "r"(a2), "r"(a3), "r"(b0), "r"(b1));
}

__device__ __forceinline__ void ldsm4(uint32_t* r, uint32_t addr) {
    asm volatile("ldmatrix.sync.aligned.m8n8.x4.shared.b16 {%0,%1,%2,%3}, [%4];"
                 : "=r"(r[0]), "=r"(r[1]), "=r"(r[2]), "=r"(r[3]) : "r"(addr));
}

__device__ __forceinline__ void cpa16(uint32_t smem_dst, const void* gsrc, int src_bytes) {
    asm volatile("cp.async.cg.shared.global [%0], [%1], 16, %2;"
                 :: "r"(smem_dst), "l"(gsrc), "r"(src_bytes));
}
__device__ __forceinline__ void cpa_commit() {
    asm volatile("cp.async.commit_group;");
}
template <int N>
__device__ __forceinline__ void cpa_wait() {
    asm volatile("cp.async.wait_group %0;" :: "n"(N));
}

// ---------------- input-role detection (content + size based) --------------
__global__ void detect_kernel(const float* p0, const float* p1, const float* p2,
                              const float* p3, const float* p4, const float* p5,
                              const float* p6, const float* p7, const float* p8,
                              long long s0, long long s1, long long s2,
                              long long s3, long long s4, long long s5,
                              long long s6, long long s7, long long s8) {
    if (threadIdx.x != 0 || blockIdx.x != 0) return;
    const float* p[9] = {p0, p1, p2, p3, p4, p5, p6, p7, p8};
    long long sz[9] = {s0, s1, s2, s3, s4, s5, s6, s7, s8};

    long long mn = sz[0];
    for (int i = 1; i < 9; i++) if (sz[i] < mn) mn = sz[i];
    long long unit = (mn == 32) ? 4 : 1;
    for (int i = 0; i < 9; i++) sz[i] /= unit;

    int pos_rb = -1, pos_rw = -1;
    int big[4]; int nb = 0;
    int med[3]; int nm = 0;
    for (int i = 0; i < 9; i++) {
        if (sz[i] == 8) pos_rb = i;
        else if (sz[i] == 8192) pos_rw = i;
        else if (sz[i] == 4194304) { if (nb < 4) big[nb] = i; nb++; }
        else if (sz[i] == 1048576) { if (nm < 3) med[nm] = i; nm++; }
    }

    bool ok = (pos_rb >= 0 && pos_rw >= 0 && nb == 4 && nm == 3);
    int pos_x = -1;
    if (ok) {
        for (int j = 0; j < 4 && pos_x < 0; j++) {
            float s = 0.f;
            const float* q = p[big[j]];
            for (int k = 0; k < 1024; k++) s += fabsf(q[k]);
            if (s * (1.f / 1024.f) > 0.1f) pos_x = big[j];
        }
        if (pos_x < 0) ok = false;
    }

    if (!ok) {
        g_ptr[0] = p[0]; g_ptr[1] = p[1]; g_ptr[2] = p[2];
        g_ptr[3] = p[3]; g_ptr[4] = p[4]; g_ptr[5] = p[5];
        g_ptr[6] = p[6]; g_ptr[7] = p[7]; g_ptr[8] = p[8];
        return;
    }

    int tr[3]; int nt = 0;
    for (int j = 0; j < 4; j++) if (big[j] != pos_x) tr[nt++] = big[j];

    g_ptr[0] = p[pos_x];
    g_ptr[1] = p[pos_rw];
    g_ptr[2] = p[pos_rb];
    if (pos_x == 0) {
        // dict-style: trios appear as (w1, w3, w2)
        g_ptr[3] = p[tr[0]]; g_ptr[4] = p[tr[1]]; g_ptr[5] = p[tr[2]];
        g_ptr[6] = p[med[0]]; g_ptr[7] = p[med[1]]; g_ptr[8] = p[med[2]];
    } else {
        // alpha-style: trios appear as (w1, w2, w3)
        g_ptr[3] = p[tr[0]]; g_ptr[4] = p[tr[2]]; g_ptr[5] = p[tr[1]];
        g_ptr[6] = p[med[0]]; g_ptr[7] = p[med[2]]; g_ptr[8] = p[med[1]];
    }
}

// ---------------- x: fp32 -> fp16 copy --------------------------------------
__global__ void xcvt_kernel() {
    int i = blockIdx.x * blockDim.x + threadIdx.x;   // float4 index (1M total)
    float4 v = ((const float4*)g_ptr[0])[i];
    __half2* dst = (__half2*)(g_wt + OFF_X);
    dst[2 * i + 0] = __floats2half2_rn(v.x, v.y);
    dst[2 * i + 1] = __floats2half2_rn(v.z, v.w);
}

// ---------------- weights: tiled TRANSPOSE + fp16 convert -------------------
// out[c][r] = half(in[r][c]).  z selects (matrix, expert).
__global__ void wtr_kernel() {
    __shared__ float tile[32][33];
    int z = blockIdx.z;
    const float* src; __half* dst; int R, C;
    if (z < 8)       { src = g_ptr[3] + (size_t)z * DIM * HID;        dst = g_wt + OFF_W1 + (size_t)z * DIM * HID;        R = DIM; C = HID; }
    else if (z < 16) { int e = z - 8;  src = g_ptr[4] + (size_t)e * DIM * HID; dst = g_wt + OFF_W3 + (size_t)e * DIM * HID; R = DIM; C = HID; }
    else if (z < 24) { int e = z - 16; src = g_ptr[5] + (size_t)e * HID * DIM; dst = g_wt + OFF_W2 + (size_t)e * HID * DIM; R = HID; C = DIM; }
    else if (z < 26) { int e = z - 24; src = g_ptr[6] + (size_t)e * DIM * HID; dst = g_wt + OFF_SW1 + (size_t)e * DIM * HID; R = DIM; C = HID; }
    else if (z < 28) { int e = z - 26; src = g_ptr[7] + (size_t)e * DIM * HID; dst = g_wt + OFF_SW3 + (size_t)e * DIM * HID; R = DIM; C = HID; }
    else             { int e = z - 28; src = g_ptr[8] + (size_t)e * HID * DIM; dst = g_wt + OFF_SW2 + (size_t)e * HID * DIM; R = HID; C = DIM; }

    int r0 = blockIdx.y * 32, c0 = blockIdx.x * 32;
    if (r0 >= R || c0 >= C) return;
    int tx = threadIdx.x, ty = threadIdx.y;
#pragma unroll
    for (int j = 0; j < 4; j++)
        tile[ty + 8 * j][tx] = src[(size_t)(r0 + ty + 8 * j) * C + c0 + tx];
    __syncthreads();
#pragma unroll
    for (int j = 0; j < 4; j++)
        dst[(size_t)(c0 + ty + 8 * j) * R + r0 + tx] = __float2half_rn(tile[tx][ty + 8 * j]);
}

// ---------------- router: logits, top-2, softmax gates (pure fp32) ---------
__global__ void router_kernel() {
    const float* x  = g_ptr[0];
    const float* rw = g_ptr[1];
    const float* rb = g_ptr[2];
    int t = blockIdx.x * blockDim.y + threadIdx.y;
    if (t >= T_TOK) return;
    int lane = threadIdx.x;
    const float* xr = x + (size_t)t * DIM;

    float acc[NE];
#pragma unroll
    for (int e = 0; e < NE; e++) acc[e] = 0.f;
    for (int i = lane; i < DIM; i += 32) {
        float xv = xr[i];
        const float* w = rw + (size_t)i * NE;
#pragma unroll
        for (int e = 0; e < NE; e++) acc[e] += xv * w[e];
    }
#pragma unroll
    for (int e = 0; e < NE; e++) {
#pragma unroll
        for (int off = 16; off > 0; off >>= 1)
            acc[e] += __shfl_xor_sync(0xffffffffu, acc[e], off);
    }
    if (lane == 0) {
        float v[NE];
#pragma unroll
        for (int e = 0; e < NE; e++) v[e] = acc[e] + rb[e];
        int i0 = 0;
        for (int e = 1; e < NE; e++) if (v[e] > v[i0]) i0 = e;
        int i1 = (i0 == 0) ? 1 : 0;
        for (int e = 0; e < NE; e++) if (e != i0 && v[e] > v[i1]) i1 = e;
        float e1 = expf(v[i1] - v[i0]);
        float g0 = 1.f / (1.f + e1);
        float g1 = e1 * g0;
        g_gates[t * 2 + 0] = g0;
        g_gates[t * 2 + 1] = g1;
        g_eidx[t * 2 + 0] = i0;
        g_eidx[t * 2 + 1] = i1;
    }
}

// ---------------- parallel smem gather: 32 warps = 8 experts x 4 segments --
__global__ void __launch_bounds__(1024) gather_kernel() {
    __shared__ int   se[T_TOK * 2];
    __shared__ float sg[T_TOK * 2];
    __shared__ int   s_cnt[32];
    __shared__ int   s_base[32];
    int tid = threadIdx.x;
    int wid = tid >> 5;
    int lane = tid & 31;

    for (int i = tid; i < T_TOK * 2; i += 1024) {
        se[i] = g_eidx[i];
        sg[i] = g_gates[i];
    }
    __syncthreads();

    int e = wid >> 2;
    int seg = wid & 3;
    int t0 = seg * (T_TOK / 4);

    int cnt = 0;
    for (int c = 0; c < T_TOK / 4; c += 32) {
        int t = t0 + c + lane;
        bool hit = (se[t * 2] == e) || (se[t * 2 + 1] == e);
        cnt += __popc(__ballot_sync(0xffffffffu, hit));
    }
    if (lane == 0) s_cnt[wid] = cnt;
    __syncthreads();
    if (tid == 0) {
        int acc = 0;
        for (int i = 0; i < 32; i++) { s_base[i] = acc; acc += s_cnt[i]; }
    }
    __syncthreads();

    int base = s_base[wid];
    int run = 0;
    for (int c = 0; c < T_TOK / 4; c += 32) {
        int t = t0 + c + lane;
        int k = -1;
        if (se[t * 2] == e) k = 0;
        else if (se[t * 2 + 1] == e) k = 1;
        unsigned mask = __ballot_sync(0xffffffffu, k >= 0);
        if (k >= 0) {
            int slot = base + run + __popc(mask & ((1u << lane) - 1u));
            g_tok[slot] = t;
            g_pos[t * 2 + k] = slot;
            g_slotgate[slot] = sg[t * 2 + k];
        }
        run += __popc(mask);
    }
    if (lane == 0 && seg == 0) g_base[e] = s_base[wid];
    if (lane == 0 && seg == 3)
        g_counts[e] = s_base[e * 4 + 3] + s_cnt[e * 4 + 3] - s_base[e * 4];
}

// ---------------- GEMM geometry ---------------------------------------------
// block 128x64, BK=64 halves, 8 warps (4x2), warp tile 32x32, m16n8k16 fp16
// A smem [m][k] pad 72 halves/row; B smem [n][k] pad 72 (weights pre-transposed)
#define PADH 72
#define A_ST (128 * PADH)   // halves per A stage
#define B_ST (64 * PADH)    // halves per B stage
#define G1_SMEM ((2 * A_ST + 4 * B_ST) * 2)
#define G2_SMEM ((2 * A_ST + 2 * B_ST) * 2)

// ---------------- GEMM1 (fp16 mma + ldmatrix): h = silu(x@w1) * (x@w3) -----
template <bool ROUTED>
__global__ void __launch_bounds__(256) gemm1_kernel() {
    extern __shared__ __half sm[];
    int e = blockIdx.z;
    int cnt  = ROUTED ? g_counts[e] : T_TOK;
    int base = ROUTED ? g_base[e] : 0;
    int row0 = blockIdx.y * 128;
    if (row0 >= cnt) return;
    int h0 = blockIdx.x * 64;

    const __half* xt  = g_wt + OFF_X;
    const __half* w1t = g_wt + (ROUTED ? OFF_W1 : OFF_SW1) + (size_t)e * DIM * HID; // [HID][DIM]
    const __half* w3t = g_wt + (ROUTED ? OFF_W3 : OFF_SW3) + (size_t)e * DIM * HID;
    __half* hout = ROUTED ? (g_h + (size_t)base * HID)
                          : (g_hsh + (size_t)e * T_TOK * HID);
    const int* toklist = ROUTED ? (g_tok + base) : nullptr;

    uint32_t sbu = (uint32_t)__cvta_generic_to_shared(sm);

    int tid = threadIdx.x;
    int lrow = tid >> 1;
    int lkc  = (tid & 1) * 32;
    int r_l = row0 + lrow;
    const __half* arow = nullptr;
    if (r_l < cnt) { int tk = ROUTED ? toklist[r_l] : r_l; arow = xt + (size_t)tk * DIM; }
    int lbrow = tid >> 2;
    int lbc   = (tid & 3) * 16;
    const __half* b1row = w1t + (size_t)(h0 + lbrow) * DIM;
    const __half* b3row = w3t + (size_t)(h0 + lbrow) * DIM;

    int wid = tid >> 5, lane = tid & 31;
    int wm = (wid >> 1) * 32;
    int wn = (wid & 1) * 32;
    int g = lane >> 2, tg = lane & 3;

    // ldmatrix per-thread offsets (halves)
    int a_r = wm + ((lane >> 3) & 1) * 8 + (lane & 7);   // A row for this lane
    int a_c = (lane >> 4) * 8;                            // A col (halves)
    int b_r = wn + (lane >> 4) * 8 + (lane & 7);          // B row (n)
    int b_c = ((lane >> 3) & 1) * 8;                      // B col (halves)

    float acc1[2][4][4], acc3[2][4][4];
#pragma unroll
    for (int i = 0; i < 2; i++)
#pragma unroll
        for (int j = 0; j < 4; j++)
#pragma unroll
            for (int c = 0; c < 4; c++) { acc1[i][j][c] = 0.f; acc3[i][j][c] = 0.f; }

    auto issue = [&](int buf, int k0) {
        uint32_t a_dst = sbu + (uint32_t)(buf * A_ST + lrow * PADH + lkc) * 2;
        const __half* a_src = arow ? (arow + k0 + lkc) : xt;
        int ab = arow ? 16 : 0;
#pragma unroll
        for (int c = 0; c < 4; c++)
            cpa16(a_dst + 16 * c, a_src + 8 * c, ab);
        uint32_t b1_dst = sbu + (uint32_t)((2 * A_ST + buf * B_ST) + lbrow * PADH + lbc) * 2;
        uint32_t b3_dst = sbu + (uint32_t)((2 * A_ST + 2 * B_ST + buf * B_ST) + lbrow * PADH + lbc) * 2;
        const __half* b1s = b1row + k0 + lbc;
        const __half* b3s = b3row + k0 + lbc;
        cpa16(b1_dst,      b1s,     16);
        cpa16(b1_dst + 16, b1s + 8, 16);
        cpa16(b3_dst,      b3s,     16);
        cpa16(b3_dst + 16, b3s + 8, 16);
        cpa_commit();
    };

    issue(0, 0);
    int buf = 0;
    const int S = DIM / 64;
    for (int s = 0; s < S; s++) {
        if (s + 1 < S) { issue(buf ^ 1, (s + 1) * 64); cpa_wait<1>(); }
        else           { cpa_wait<0>(); }
        __syncthreads();
        uint32_t aB  = sbu + (uint32_t)(buf * A_ST + a_r * PADH + a_c) * 2;
        uint32_t b1B = sbu + (uint32_t)(2 * A_ST + buf * B_ST + b_r * PADH + b_c) * 2;
        uint32_t b3B = b1B + (uint32_t)(2 * B_ST) * 2;
        const uint32_t rowskip = (uint32_t)(16 * PADH) * 2;
#pragma unroll
        for (int kk4 = 0; kk4 < 4; kk4++) {
            uint32_t ka = kk4 * 32;     // 16 halves
            uint32_t a0[4], a1[4];
            ldsm4(a0, aB + ka);
            ldsm4(a1, aB + rowskip + ka);
            uint32_t p01[4], p23[4], q01[4], q23[4];
            ldsm4(p01, b1B + ka);
            ldsm4(p23, b1B + rowskip + ka);
            ldsm4(q01, b3B + ka);
            ldsm4(q23, b3B + rowskip + ka);
#pragma unroll
            for (int j = 0; j < 4; j++) {
                const uint32_t* pb = (j < 2) ? p01 : p23;
                const uint32_t* qb = (j < 2) ? q01 : q23;
                int s2 = (j & 1) * 2;
                mma_f16(acc1[0][j], a0[0], a0[1], a0[2], a0[3], pb[s2], pb[s2 + 1]);
                mma_f16(acc1[1][j], a1[0], a1[1], a1[2], a1[3], pb[s2], pb[s2 + 1]);
                mma_f16(acc3[0][j], a0[0], a0[1], a0[2], a0[3], qb[s2], qb[s2 + 1]);
                mma_f16(acc3[1][j], a1[0], a1[1], a1[2], a1[3], qb[s2], qb[s2 + 1]);
            }
        }
        __syncthreads();
        buf ^= 1;
    }

#pragma unroll
    for (int i = 0; i < 2; i++) {
        int r0 = row0 + wm + i * 16 + g;
        int r1 = r0 + 8;
#pragma unroll
        for (int j = 0; j < 4; j++) {
            int c = h0 + wn + j * 8 + 2 * tg;
            if (r0 < cnt) {
                float v0 = acc1[i][j][0], v1 = acc1[i][j][1];
                *(__half2*)(hout + (size_t)r0 * HID + c) = __floats2half2_rn(
                    (v0 / (1.f + expf(-v0))) * acc3[i][j][0],
                    (v1 / (1.f + expf(-v1))) * acc3[i][j][1]);
            }
            if (r1 < cnt) {
                float v2 = acc1[i][j][2], v3 = acc1[i][j][3];
                *(__half2*)(hout + (size_t)r1 * HID + c) = __floats2half2_rn(
                    (v2 / (1.f + expf(-v2))) * acc3[i][j][2],
                    (v3 / (1.f + expf(-v3))) * acc3[i][j][3]);
            }
        }
    }
}

// ---------------- GEMM2 (fp16 mma + ldmatrix) --------------------------------
// ROUTED: g_y[slot] = (h @ w2) * gate ; !ROUTED: out = sum_s hsh@sw2 + combine
template <bool ROUTED>
__global__ void __launch_bounds__(256) gemm2_kernel(float* __restrict__ out) {
    extern __shared__ __half sm[];
    int e = blockIdx.z;
    int cnt  = ROUTED ? g_counts[e] : T_TOK;
    int base = ROUTED ? g_base[e] : 0;
    int row0 = blockIdx.y * 128;
    if (row0 >= cnt) return;
    int d0 = blockIdx.x * 64;

    uint32_t sbu = (uint32_t)__cvta_generic_to_shared(sm);

    int tid = threadIdx.x;
    int lrow = tid >> 1;
    int lkc  = (tid & 1) * 32;
    int r_l = row0 + lrow;
    bool aval = (r_l < cnt);
    int lbrow = tid >> 2;
    int lbc   = (tid & 3) * 16;

    int wid = tid >> 5, lane = tid & 31;
    int wm = (wid >> 1) * 32;
    int wn = (wid & 1) * 32;
    int g = lane >> 2, tg = lane & 3;

    int a_r = wm + ((lane >> 3) & 1) * 8 + (lane & 7);
    int a_c = (lane >> 4) * 8;
    int b_r = wn + (lane >> 4) * 8 + (lane & 7);
    int b_c = ((lane >> 3) & 1) * 8;

    float acc[2][4][4];
#pragma unroll
    for (int i = 0; i < 2; i++)
#pragma unroll
        for (int j = 0; j < 4; j++)
#pragma unroll
            for (int c = 0; c < 4; c++) acc[i][j][c] = 0.f;

    int total_k = (ROUTED ? 1 : NSH) * HID;

    auto issue = [&](int buf, int k0) {
        int seg = k0 >> 9;
        int kl = k0 & (HID - 1);
        const __half* A = ROUTED ? (g_h + (size_t)base * HID)
                                 : (g_hsh + (size_t)seg * T_TOK * HID);
        const __half* w2t = g_wt + (ROUTED ? OFF_W2 : OFF_SW2)
                          + (size_t)(ROUTED ? e : seg) * HID * DIM;   // [DIM][HID]
        uint32_t a_dst = sbu + (uint32_t)(buf * A_ST + lrow * PADH + lkc) * 2;
        const __half* a_src = aval ? (A + (size_t)r_l * HID + kl + lkc) : A;
        int ab = aval ? 16 : 0;
#pragma unroll
        for (int c = 0; c < 4; c++)
            cpa16(a_dst + 16 * c, a_src + 8 * c, ab);
        uint32_t b_dst = sbu + (uint32_t)((2 * A_ST + buf * B_ST) + lbrow * PADH + lbc) * 2;
        const __half* b_src = w2t + (size_t)(d0 + lbrow) * HID + kl + lbc;
        cpa16(b_dst,      b_src,     16);
        cpa16(b_dst + 16, b_src + 8, 16);
        cpa_commit();
    };

    issue(0, 0);
    int buf = 0;
    const int S = total_k / 64;
    for (int s = 0; s < S; s++) {
        if (s + 1 < S) { issue(buf ^ 1, (s + 1) * 64); cpa_wait<1>(); }
        else           { cpa_wait<0>(); }
        __syncthreads();
        uint32_t aB = sbu + (uint32_t)(buf * A_ST + a_r * PADH + a_c) * 2;
        uint32_t bB = sbu + (uint32_t)(2 * A_ST + buf * B_ST + b_r * PADH + b_c) * 2;
        const uint32_t rowskip = (uint32_t)(16 * PADH) * 2;
#pragma unroll
        for (int kk4 = 0; kk4 < 4; kk4++) {
            uint32_t ka = kk4 * 32;
            uint32_t a0[4], a1[4];
            ldsm4(a0, aB + ka);
            ldsm4(a1, aB + rowskip + ka);
            uint32_t p01[4], p23[4];
            ldsm4(p01, bB + ka);
            ldsm4(p23, bB + rowskip + ka);
#pragma unroll
            for (int j = 0; j < 4; j++) {
                const uint32_t* pb = (j < 2) ? p01 : p23;
                int s2 = (j & 1) * 2;
                mma_f16(acc[0][j], a0[0], a0[1], a0[2], a0[3], pb[s2], pb[s2 + 1]);
                mma_f16(acc[1][j], a1[0], a1[1], a1[2], a1[3], pb[s2], pb[s2 + 1]);
            }
        }
        __syncthreads();
        buf ^= 1;
    }

#pragma unroll
    for (int i = 0; i < 2; i++) {
        int r0 = row0 + wm + i * 16 + g;
        int r1 = r0 + 8;
        if (ROUTED) {
            float sc0 = (r0 < cnt) ? g_slotgate[base + r0] : 1.f;
            float sc1 = (r1 < cnt) ? g_slotgate[base + r1] : 1.f;
#pragma unroll
            for (int j = 0; j < 4; j++) {
                int c = d0 + wn + j * 8 + 2 * tg;
                if (r0 < cnt) {
                    float2 o;
                    o.x = acc[i][j][0] * sc0;
                    o.y = acc[i][j][1] * sc0;
                    *(float2*)(g_y + (size_t)(base + r0) * DIM + c) = o;
                }
                if (r1 < cnt) {
                    float2 o;
                    o.x = acc[i][j][2] * sc1;
                    o.y = acc[i][j][3] * sc1;
                    *(float2*)(g_y + (size_t)(base + r1) * DIM + c) = o;
                }
            }
        } else {
            int p00 = g_pos[r0 * 2 + 0], p01 = g_pos[r0 * 2 + 1];
            int p10 = g_pos[r1 * 2 + 0], p11 = g_pos[r1 * 2 + 1];
#pragma unroll
            for (int j = 0; j < 4; j++) {
                int c = d0 + wn + j * 8 + 2 * tg;
                float2 a0 = *(const float2*)(g_y + (size_t)p00 * DIM + c);
                float2 a1 = *(const float2*)(g_y + (size_t)p01 * DIM + c);
                float2 b0 = *(const float2*)(g_y + (size_t)p10 * DIM + c);
                float2 b1 = *(const float2*)(g_y + (size_t)p11 * DIM + c);
                float2 o0, o1;
                o0.x = acc[i][j][0] + a0.x + a1.x;
                o0.y = acc[i][j][1] + a0.y + a1.y;
                o1.x = acc[i][j][2] + b0.x + b1.x;
                o1.y = acc[i][j][3] + b0.y + b1.y;
                *(float2*)(out + (size_t)r0 * DIM + c) = o0;
                *(float2*)(out + (size_t)r1 * DIM + c) = o1;
            }
        }
    }
}

// ---------------- launcher (fork-join two-stream schedule) -----------------
extern "C" void kernel_launch(void* const* d_in, const int* in_sizes, int n_in,
                              void* d_out, int out_size) {
    static cudaStream_t s1 = nullptr;
    static cudaEvent_t evDet = nullptr, evCvt = nullptr, evGat = nullptr, evSh = nullptr;
    if (s1 == nullptr) {
        cudaFuncSetAttribute(gemm1_kernel<true>,
                             cudaFuncAttributeMaxDynamicSharedMemorySize, G1_SMEM);
        cudaFuncSetAttribute(gemm1_kernel<false>,
                             cudaFuncAttributeMaxDynamicSharedMemorySize, G1_SMEM);
        cudaFuncSetAttribute(gemm2_kernel<true>,
                             cudaFuncAttributeMaxDynamicSharedMemorySize, G2_SMEM);
        cudaFuncSetAttribute(gemm2_kernel<false>,
                             cudaFuncAttributeMaxDynamicSharedMemorySize, G2_SMEM);
        cudaStreamCreateWithFlags(&s1, cudaStreamNonBlocking);
        cudaEventCreateWithFlags(&evDet, cudaEventDisableTiming);
        cudaEventCreateWithFlags(&evCvt, cudaEventDisableTiming);
        cudaEventCreateWithFlags(&evGat, cudaEventDisableTiming);
        cudaEventCreateWithFlags(&evSh,  cudaEventDisableTiming);
    }

    detect_kernel<<<1, 32>>>(
        (const float*)d_in[0], (const float*)d_in[1], (const float*)d_in[2],
        (const float*)d_in[3], (const float*)d_in[4], (const float*)d_in[5],
        (const float*)d_in[6], (const float*)d_in[7], (const float*)d_in[8],
        (long long)in_sizes[0], (long long)in_sizes[1], (long long)in_sizes[2],
        (long long)in_sizes[3], (long long)in_sizes[4], (long long)in_sizes[5],
        (long long)in_sizes[6], (long long)in_sizes[7], (long long)in_sizes[8]);
    cudaEventRecord(evDet, 0);

    // s1: router + gather (reads original fp32 x)
    cudaStreamWaitEvent(s1, evDet, 0);
    router_kernel<<<T_TOK / 4, dim3(32, 4), 0, s1>>>();
    gather_kernel<<<1, 1024, 0, s1>>>();
    cudaEventRecord(evGat, s1);

    // s0: fp16 conversion (x copy + weight transpose) — overlaps router+gather
    xcvt_kernel<<<T_TOK * DIM / 4 / 256, 256>>>();
    wtr_kernel<<<dim3(32, 32, 30), dim3(32, 8)>>>();
    cudaEventRecord(evCvt, 0);

    // s1: shared-expert gemm1 (needs cvt only) — overlaps routed path
    cudaStreamWaitEvent(s1, evCvt, 0);
    gemm1_kernel<false><<<dim3(HID / 64, T_TOK / 128, NSH), 256, G1_SMEM, s1>>>();
    cudaEventRecord(evSh, s1);

    // s0: routed path (needs gather + cvt)
    cudaStreamWaitEvent(0, evGat, 0);
    gemm1_kernel<true><<<dim3(HID / 64, T_TOK / 128, NE), 256, G1_SMEM>>>();
    gemm2_kernel<true><<<dim3(DIM / 64, T_TOK / 128, NE), 256, G2_SMEM>>>(nullptr);

    // s0: fused shared gemm2 + combine
    cudaStreamWaitEvent(0, evSh, 0);
    gemm2_kernel<false><<<dim3(DIM / 64, T_TOK / 128, 1), 256, G2_SMEM>>>((float*)d_out);
}

// round 13
// speedup vs baseline: 1.0740x; 1.0740x over previous
#include <cuda_runtime.h>
#include <cuda_fp16.h>
#include <math.h>
#include <stdint.h>

#define T_TOK 4096
#define DIM   1024
#define HID   512
#define NE    8
#define NSH   2
#define NSLOT (2 * T_TOK)

// offsets (halves) inside g_wt scratch; weights stored TRANSPOSED [n][k] fp16
#define OFF_X   0
#define OFF_W1  4194304
#define OFF_W3  8388608
#define OFF_W2  12582912
#define OFF_SW1 16777216
#define OFF_SW3 17825792
#define OFF_SW2 18874368
#define WT_TOTAL 19922944   // halves (38 MB)

// ---------------- scratch (device globals; no runtime allocation) ----------
// pointer role table: 0=x 1=router_w 2=router_b 3=w1 4=w3 5=w2 6=sw1 7=sw3 8=sw2
__device__ const float* g_ptr[9];

__device__ __align__(16) __half g_wt[WT_TOTAL];
__device__ __align__(16) float  g_gates[T_TOK * 2];
__device__ __align__(16) int    g_eidx[T_TOK * 2];
__device__ __align__(16) int    g_counts[NE];
__device__ __align__(16) int    g_base[NE];
__device__ __align__(16) int    g_tok[NSLOT];
__device__ __align__(16) float  g_slotgate[NSLOT];
__device__ __align__(16) __half g_h[(size_t)NSLOT * HID];        // 8 MB fp16
__device__ __align__(16) __half g_hsh[(size_t)NSH * T_TOK * HID];// 8 MB fp16

// ---------------- helpers ---------------------------------------------------
__device__ __forceinline__ void mma_f16(float c[4],
                                        uint32_t a0, uint32_t a1, uint32_t a2, uint32_t a3,
                                        uint32_t b0, uint32_t b1) {
    asm volatile(
        "mma.sync.aligned.m16n8k16.row.col.f32.f16.f16.f32 "
        "{%0,%1,%2,%3},{%4,%5,%6,%7},{%8,%9},{%0,%1,%2,%3};"
        : "+f"(c[0]), "+f"(c[1]), "+f"(c[2]), "+f"(c[3])
        : "r"(a0), "r"(a1), "r"(a2), "r"(a3), "r"(b0), "r"(b1));
}

__device__ __forceinline__ void cpa16(uint32_t smem_dst, const void* gsrc, int src_bytes) {
    asm volatile("cp.async.cg.shared.global [%0], [%1], 16, %2;"
                 :: "r"(smem_dst), "l"(gsrc), "r"(src_bytes));
}
__device__ __forceinline__ void cpa_commit() {
    asm volatile("cp.async.commit_group;");
}
template <int N>
__device__ __forceinline__ void cpa_wait() {
    asm volatile("cp.async.wait_group %0;" :: "n"(N));
}

// ---------------- input-role detection (content + size based) --------------
__global__ void detect_kernel(const float* p0, const float* p1, const float* p2,
                              const float* p3, const float* p4, const float* p5,
                              const float* p6, const float* p7, const float* p8,
                              long long s0, long long s1, long long s2,
                              long long s3, long long s4, long long s5,
                              long long s6, long long s7, long long s8) {
    if (threadIdx.x != 0 || blockIdx.x != 0) return;
    const float* p[9] = {p0, p1, p2, p3, p4, p5, p6, p7, p8};
    long long sz[9] = {s0, s1, s2, s3, s4, s5, s6, s7, s8};

    long long mn = sz[0];
    for (int i = 1; i < 9; i++) if (sz[i] < mn) mn = sz[i];
    long long unit = (mn == 32) ? 4 : 1;
    for (int i = 0; i < 9; i++) sz[i] /= unit;

    int pos_rb = -1, pos_rw = -1;
    int big[4]; int nb = 0;
    int med[3]; int nm = 0;
    for (int i = 0; i < 9; i++) {
        if (sz[i] == 8) pos_rb = i;
        else if (sz[i] == 8192) pos_rw = i;
        else if (sz[i] == 4194304) { if (nb < 4) big[nb] = i; nb++; }
        else if (sz[i] == 1048576) { if (nm < 3) med[nm] = i; nm++; }
    }

    bool ok = (pos_rb >= 0 && pos_rw >= 0 && nb == 4 && nm == 3);
    int pos_x = -1;
    if (ok) {
        for (int j = 0; j < 4 && pos_x < 0; j++) {
            float s = 0.f;
            const float* q = p[big[j]];
            for (int k = 0; k < 1024; k++) s += fabsf(q[k]);
            if (s * (1.f / 1024.f) > 0.1f) pos_x = big[j];
        }
        if (pos_x < 0) ok = false;
    }

    if (!ok) {
        g_ptr[0] = p[0]; g_ptr[1] = p[1]; g_ptr[2] = p[2];
        g_ptr[3] = p[3]; g_ptr[4] = p[4]; g_ptr[5] = p[5];
        g_ptr[6] = p[6]; g_ptr[7] = p[7]; g_ptr[8] = p[8];
        return;
    }

    int tr[3]; int nt = 0;
    for (int j = 0; j < 4; j++) if (big[j] != pos_x) tr[nt++] = big[j];

    g_ptr[0] = p[pos_x];
    g_ptr[1] = p[pos_rw];
    g_ptr[2] = p[pos_rb];
    if (pos_x == 0) {
        // dict-style: trios appear as (w1, w3, w2)
        g_ptr[3] = p[tr[0]]; g_ptr[4] = p[tr[1]]; g_ptr[5] = p[tr[2]];
        g_ptr[6] = p[med[0]]; g_ptr[7] = p[med[1]]; g_ptr[8] = p[med[2]];
    } else {
        // alpha-style: trios appear as (w1, w2, w3)
        g_ptr[3] = p[tr[0]]; g_ptr[4] = p[tr[2]]; g_ptr[5] = p[tr[1]];
        g_ptr[6] = p[med[0]]; g_ptr[7] = p[med[2]]; g_ptr[8] = p[med[1]];
    }
}

// ---------------- x: fp32 -> fp16 copy --------------------------------------
__global__ void xcvt_kernel() {
    int i = blockIdx.x * blockDim.x + threadIdx.x;   // float4 index (1M total)
    float4 v = ((const float4*)g_ptr[0])[i];
    __half2* dst = (__half2*)(g_wt + OFF_X);
    dst[2 * i + 0] = __floats2half2_rn(v.x, v.y);
    dst[2 * i + 1] = __floats2half2_rn(v.z, v.w);
}

// ---------------- weights: tiled TRANSPOSE + fp16 convert -------------------
// out[c][r] = half(in[r][c]).  z selects (matrix, expert).
__global__ void wtr_kernel() {
    __shared__ float tile[32][33];
    int z = blockIdx.z;
    const float* src; __half* dst; int R, C;
    if (z < 8)       { src = g_ptr[3] + (size_t)z * DIM * HID;        dst = g_wt + OFF_W1 + (size_t)z * DIM * HID;        R = DIM; C = HID; }
    else if (z < 16) { int e = z - 8;  src = g_ptr[4] + (size_t)e * DIM * HID; dst = g_wt + OFF_W3 + (size_t)e * DIM * HID; R = DIM; C = HID; }
    else if (z < 24) { int e = z - 16; src = g_ptr[5] + (size_t)e * HID * DIM; dst = g_wt + OFF_W2 + (size_t)e * HID * DIM; R = HID; C = DIM; }
    else if (z < 26) { int e = z - 24; src = g_ptr[6] + (size_t)e * DIM * HID; dst = g_wt + OFF_SW1 + (size_t)e * DIM * HID; R = DIM; C = HID; }
    else if (z < 28) { int e = z - 26; src = g_ptr[7] + (size_t)e * DIM * HID; dst = g_wt + OFF_SW3 + (size_t)e * DIM * HID; R = DIM; C = HID; }
    else             { int e = z - 28; src = g_ptr[8] + (size_t)e * HID * DIM; dst = g_wt + OFF_SW2 + (size_t)e * HID * DIM; R = HID; C = DIM; }

    int r0 = blockIdx.y * 32, c0 = blockIdx.x * 32;
    if (r0 >= R || c0 >= C) return;
    int tx = threadIdx.x, ty = threadIdx.y;
#pragma unroll
    for (int j = 0; j < 4; j++)
        tile[ty + 8 * j][tx] = src[(size_t)(r0 + ty + 8 * j) * C + c0 + tx];
    __syncthreads();
#pragma unroll
    for (int j = 0; j < 4; j++)
        dst[(size_t)(c0 + ty + 8 * j) * R + r0 + tx] = __float2half_rn(tile[tx][ty + 8 * j]);
}

// ---------------- router: logits, top-2, softmax gates (pure fp32) ---------
__global__ void router_kernel() {
    const float* x  = g_ptr[0];
    const float* rw = g_ptr[1];
    const float* rb = g_ptr[2];
    int t = blockIdx.x * blockDim.y + threadIdx.y;
    if (t >= T_TOK) return;
    int lane = threadIdx.x;
    const float* xr = x + (size_t)t * DIM;

    float acc[NE];
#pragma unroll
    for (int e = 0; e < NE; e++) acc[e] = 0.f;
    for (int i = lane; i < DIM; i += 32) {
        float xv = xr[i];
        const float* w = rw + (size_t)i * NE;
#pragma unroll
        for (int e = 0; e < NE; e++) acc[e] += xv * w[e];
    }
#pragma unroll
    for (int e = 0; e < NE; e++) {
#pragma unroll
        for (int off = 16; off > 0; off >>= 1)
            acc[e] += __shfl_xor_sync(0xffffffffu, acc[e], off);
    }
    if (lane == 0) {
        float v[NE];
#pragma unroll
        for (int e = 0; e < NE; e++) v[e] = acc[e] + rb[e];
        int i0 = 0;
        for (int e = 1; e < NE; e++) if (v[e] > v[i0]) i0 = e;
        int i1 = (i0 == 0) ? 1 : 0;
        for (int e = 0; e < NE; e++) if (e != i0 && v[e] > v[i1]) i1 = e;
        float e1 = expf(v[i1] - v[i0]);
        float g0 = 1.f / (1.f + e1);
        float g1 = e1 * g0;
        g_gates[t * 2 + 0] = g0;
        g_gates[t * 2 + 1] = g1;
        g_eidx[t * 2 + 0] = i0;
        g_eidx[t * 2 + 1] = i1;
    }
}

// ---------------- parallel smem gather: 32 warps = 8 experts x 4 segments --
__global__ void __launch_bounds__(1024) gather_kernel() {
    __shared__ int   se[T_TOK * 2];
    __shared__ float sg[T_TOK * 2];
    __shared__ int   s_cnt[32];
    __shared__ int   s_base[32];
    int tid = threadIdx.x;
    int wid = tid >> 5;
    int lane = tid & 31;

    for (int i = tid; i < T_TOK * 2; i += 1024) {
        se[i] = g_eidx[i];
        sg[i] = g_gates[i];
    }
    __syncthreads();

    int e = wid >> 2;
    int seg = wid & 3;
    int t0 = seg * (T_TOK / 4);

    int cnt = 0;
    for (int c = 0; c < T_TOK / 4; c += 32) {
        int t = t0 + c + lane;
        bool hit = (se[t * 2] == e) || (se[t * 2 + 1] == e);
        cnt += __popc(__ballot_sync(0xffffffffu, hit));
    }
    if (lane == 0) s_cnt[wid] = cnt;
    __syncthreads();
    if (tid == 0) {
        int acc = 0;
        for (int i = 0; i < 32; i++) { s_base[i] = acc; acc += s_cnt[i]; }
    }
    __syncthreads();

    int base = s_base[wid];
    int run = 0;
    for (int c = 0; c < T_TOK / 4; c += 32) {
        int t = t0 + c + lane;
        int k = -1;
        if (se[t * 2] == e) k = 0;
        else if (se[t * 2 + 1] == e) k = 1;
        unsigned mask = __ballot_sync(0xffffffffu, k >= 0);
        if (k >= 0) {
            int slot = base + run + __popc(mask & ((1u << lane) - 1u));
            g_tok[slot] = t;
            g_slotgate[slot] = sg[t * 2 + k];
        }
        run += __popc(mask);
    }
    if (lane == 0 && seg == 0) g_base[e] = s_base[wid];
    if (lane == 0 && seg == 3)
        g_counts[e] = s_base[e * 4 + 3] + s_cnt[e * 4 + 3] - s_base[e * 4];
}

// ---------------- GEMM geometry ---------------------------------------------
// block 128x64, BK=64 halves, 8 warps (4x2), warp tile 32x32, m16n8k16 fp16
// A smem [m][k] pad 72 halves/row; B smem [n][k] pad 72 (weights pre-transposed)
#define PADH 72
#define A_ST (128 * PADH)   // halves per A stage
#define B_ST (64 * PADH)    // halves per B stage
#define G1_SMEM ((2 * A_ST + 4 * B_ST) * 2)
#define G2_SMEM ((2 * A_ST + 2 * B_ST) * 2)

// ---------------- GEMM1 (fp16 mma): h = silu(x@w1) * (x@w3) ----------------
template <bool ROUTED>
__global__ void __launch_bounds__(256) gemm1_kernel() {
    extern __shared__ __half sm[];
    int e = blockIdx.z;
    int cnt  = ROUTED ? g_counts[e] : T_TOK;
    int base = ROUTED ? g_base[e] : 0;
    int row0 = blockIdx.y * 128;
    if (row0 >= cnt) return;
    int h0 = blockIdx.x * 64;

    const __half* xt  = g_wt + OFF_X;
    const __half* w1t = g_wt + (ROUTED ? OFF_W1 : OFF_SW1) + (size_t)e * DIM * HID; // [HID][DIM]
    const __half* w3t = g_wt + (ROUTED ? OFF_W3 : OFF_SW3) + (size_t)e * DIM * HID;
    __half* hout = ROUTED ? (g_h + (size_t)base * HID)
                          : (g_hsh + (size_t)e * T_TOK * HID);
    const int* toklist = ROUTED ? (g_tok + base) : nullptr;

    uint32_t sbu = (uint32_t)__cvta_generic_to_shared(sm);
    const uint32_t* Asw = (const uint32_t*)sm;
    const uint32_t* B1w = (const uint32_t*)(sm + 2 * A_ST);
    const uint32_t* B3w = (const uint32_t*)(sm + 2 * A_ST + 2 * B_ST);

    int tid = threadIdx.x;
    int lrow = tid >> 1;
    int lkc  = (tid & 1) * 32;
    int r_l = row0 + lrow;
    const __half* arow = nullptr;
    if (r_l < cnt) { int tk = ROUTED ? toklist[r_l] : r_l; arow = xt + (size_t)tk * DIM; }
    int lbrow = tid >> 2;
    int lbc   = (tid & 3) * 16;
    const __half* b1row = w1t + (size_t)(h0 + lbrow) * DIM;
    const __half* b3row = w3t + (size_t)(h0 + lbrow) * DIM;

    int wid = tid >> 5, lane = tid & 31;
    int wm = (wid >> 1) * 32;
    int wn = (wid & 1) * 32;
    int g = lane >> 2, tg = lane & 3;

    float acc1[2][4][4], acc3[2][4][4];
#pragma unroll
    for (int i = 0; i < 2; i++)
#pragma unroll
        for (int j = 0; j < 4; j++)
#pragma unroll
            for (int c = 0; c < 4; c++) { acc1[i][j][c] = 0.f; acc3[i][j][c] = 0.f; }

    auto issue = [&](int buf, int k0) {
        uint32_t a_dst = sbu + (uint32_t)(buf * A_ST + lrow * PADH + lkc) * 2;
        const __half* a_src = arow ? (arow + k0 + lkc) : xt;
        int ab = arow ? 16 : 0;
#pragma unroll
        for (int c = 0; c < 4; c++)
            cpa16(a_dst + 16 * c, a_src + 8 * c, ab);
        uint32_t b1_dst = sbu + (uint32_t)((2 * A_ST + buf * B_ST) + lbrow * PADH + lbc) * 2;
        uint32_t b3_dst = sbu + (uint32_t)((2 * A_ST + 2 * B_ST + buf * B_ST) + lbrow * PADH + lbc) * 2;
        const __half* b1s = b1row + k0 + lbc;
        const __half* b3s = b3row + k0 + lbc;
        cpa16(b1_dst,      b1s,     16);
        cpa16(b1_dst + 16, b1s + 8, 16);
        cpa16(b3_dst,      b3s,     16);
        cpa16(b3_dst + 16, b3s + 8, 16);
        cpa_commit();
    };

    issue(0, 0);
    int buf = 0;
    const int S = DIM / 64;
    for (int s = 0; s < S; s++) {
        if (s + 1 < S) { issue(buf ^ 1, (s + 1) * 64); cpa_wait<1>(); }
        else           { cpa_wait<0>(); }
        __syncthreads();
        const uint32_t* Ab  = Asw + buf * (A_ST / 2);
        const uint32_t* B1b = B1w + buf * (B_ST / 2);
        const uint32_t* B3b = B3w + buf * (B_ST / 2);
#pragma unroll
        for (int kk4 = 0; kk4 < 4; kk4++) {
            uint32_t a[2][4];
#pragma unroll
            for (int i = 0; i < 2; i++) {
                int m = wm + i * 16 + g;
                int bidx = m * (PADH / 2) + kk4 * 8 + tg;
                a[i][0] = Ab[bidx];
                a[i][1] = Ab[bidx + 8 * (PADH / 2)];
                a[i][2] = Ab[bidx + 4];
                a[i][3] = Ab[bidx + 8 * (PADH / 2) + 4];
            }
#pragma unroll
            for (int j = 0; j < 4; j++) {
                int n = wn + j * 8 + g;
                int nb = n * (PADH / 2) + kk4 * 8 + tg;
                uint32_t p0 = B1b[nb], p1 = B1b[nb + 4];
                uint32_t q0 = B3b[nb], q1 = B3b[nb + 4];
#pragma unroll
                for (int i = 0; i < 2; i++) {
                    mma_f16(acc1[i][j], a[i][0], a[i][1], a[i][2], a[i][3], p0, p1);
                    mma_f16(acc3[i][j], a[i][0], a[i][1], a[i][2], a[i][3], q0, q1);
                }
            }
        }
        __syncthreads();
        buf ^= 1;
    }

#pragma unroll
    for (int i = 0; i < 2; i++) {
        int r0 = row0 + wm + i * 16 + g;
        int r1 = r0 + 8;
#pragma unroll
        for (int j = 0; j < 4; j++) {
            int c = h0 + wn + j * 8 + 2 * tg;
            if (r0 < cnt) {
                float v0 = acc1[i][j][0], v1 = acc1[i][j][1];
                *(__half2*)(hout + (size_t)r0 * HID + c) = __floats2half2_rn(
                    (v0 / (1.f + expf(-v0))) * acc3[i][j][0],
                    (v1 / (1.f + expf(-v1))) * acc3[i][j][1]);
            }
            if (r1 < cnt) {
                float v2 = acc1[i][j][2], v3 = acc1[i][j][3];
                *(__half2*)(hout + (size_t)r1 * HID + c) = __floats2half2_rn(
                    (v2 / (1.f + expf(-v2))) * acc3[i][j][2],
                    (v3 / (1.f + expf(-v3))) * acc3[i][j][3]);
            }
        }
    }
}

// ---------------- GEMM2 (fp16 mma) ------------------------------------------
// ROUTED: atomicAdd gate*(h@w2) into out[token] ; !ROUTED: out = sum_s hsh@sw2
template <bool ROUTED>
__global__ void __launch_bounds__(256) gemm2_kernel(float* __restrict__ out) {
    extern __shared__ __half sm[];
    int e = blockIdx.z;
    int cnt  = ROUTED ? g_counts[e] : T_TOK;
    int base = ROUTED ? g_base[e] : 0;
    int row0 = blockIdx.y * 128;
    if (row0 >= cnt) return;
    int d0 = blockIdx.x * 64;

    uint32_t sbu = (uint32_t)__cvta_generic_to_shared(sm);
    const uint32_t* Asw = (const uint32_t*)sm;
    const uint32_t* Bw  = (const uint32_t*)(sm + 2 * A_ST);

    int tid = threadIdx.x;
    int lrow = tid >> 1;
    int lkc  = (tid & 1) * 32;
    int r_l = row0 + lrow;
    bool aval = (r_l < cnt);
    int lbrow = tid >> 2;
    int lbc   = (tid & 3) * 16;

    int wid = tid >> 5, lane = tid & 31;
    int wm = (wid >> 1) * 32;
    int wn = (wid & 1) * 32;
    int g = lane >> 2, tg = lane & 3;

    float acc[2][4][4];
#pragma unroll
    for (int i = 0; i < 2; i++)
#pragma unroll
        for (int j = 0; j < 4; j++)
#pragma unroll
            for (int c = 0; c < 4; c++) acc[i][j][c] = 0.f;

    int total_k = (ROUTED ? 1 : NSH) * HID;

    auto issue = [&](int buf, int k0) {
        int seg = k0 >> 9;
        int kl = k0 & (HID - 1);
        const __half* A = ROUTED ? (g_h + (size_t)base * HID)
                                 : (g_hsh + (size_t)seg * T_TOK * HID);
        const __half* w2t = g_wt + (ROUTED ? OFF_W2 : OFF_SW2)
                          + (size_t)(ROUTED ? e : seg) * HID * DIM;   // [DIM][HID]
        uint32_t a_dst = sbu + (uint32_t)(buf * A_ST + lrow * PADH + lkc) * 2;
        const __half* a_src = aval ? (A + (size_t)r_l * HID + kl + lkc) : A;
        int ab = aval ? 16 : 0;
#pragma unroll
        for (int c = 0; c < 4; c++)
            cpa16(a_dst + 16 * c, a_src + 8 * c, ab);
        uint32_t b_dst = sbu + (uint32_t)((2 * A_ST + buf * B_ST) + lbrow * PADH + lbc) * 2;
        const __half* b_src = w2t + (size_t)(d0 + lbrow) * HID + kl + lbc;
        cpa16(b_dst,      b_src,     16);
        cpa16(b_dst + 16, b_src + 8, 16);
        cpa_commit();
    };

    issue(0, 0);
    int buf = 0;
    const int S = total_k / 64;
    for (int s = 0; s < S; s++) {
        if (s + 1 < S) { issue(buf ^ 1, (s + 1) * 64); cpa_wait<1>(); }
        else           { cpa_wait<0>(); }
        __syncthreads();
        const uint32_t* Ab = Asw + buf * (A_ST / 2);
        const uint32_t* Bb = Bw + buf * (B_ST / 2);
#pragma unroll
        for (int kk4 = 0; kk4 < 4; kk4++) {
            uint32_t a[2][4];
#pragma unroll
            for (int i = 0; i < 2; i++) {
                int m = wm + i * 16 + g;
                int bidx = m * (PADH / 2) + kk4 * 8 + tg;
                a[i][0] = Ab[bidx];
                a[i][1] = Ab[bidx + 8 * (PADH / 2)];
                a[i][2] = Ab[bidx + 4];
                a[i][3] = Ab[bidx + 8 * (PADH / 2) + 4];
            }
#pragma unroll
            for (int j = 0; j < 4; j++) {
                int n = wn + j * 8 + g;
                int nb = n * (PADH / 2) + kk4 * 8 + tg;
                uint32_t p0 = Bb[nb], p1 = Bb[nb + 4];
#pragma unroll
                for (int i = 0; i < 2; i++)
                    mma_f16(acc[i][j], a[i][0], a[i][1], a[i][2], a[i][3], p0, p1);
            }
        }
        __syncthreads();
        buf ^= 1;
    }

#pragma unroll
    for (int i = 0; i < 2; i++) {
        int r0 = row0 + wm + i * 16 + g;
        int r1 = r0 + 8;
        if (ROUTED) {
            // scatter gated contributions directly into out via atomics
            float sc0 = 0.f, sc1 = 0.f;
            int t0 = 0, t1 = 0;
            if (r0 < cnt) { sc0 = g_slotgate[base + r0]; t0 = g_tok[base + r0]; }
            if (r1 < cnt) { sc1 = g_slotgate[base + r1]; t1 = g_tok[base + r1]; }
#pragma unroll
            for (int j = 0; j < 4; j++) {
                int c = d0 + wn + j * 8 + 2 * tg;
                if (r0 < cnt) {
                    atomicAdd(out + (size_t)t0 * DIM + c,     acc[i][j][0] * sc0);
                    atomicAdd(out + (size_t)t0 * DIM + c + 1, acc[i][j][1] * sc0);
                }
                if (r1 < cnt) {
                    atomicAdd(out + (size_t)t1 * DIM + c,     acc[i][j][2] * sc1);
                    atomicAdd(out + (size_t)t1 * DIM + c + 1, acc[i][j][3] * sc1);
                }
            }
        } else {
            // shared-expert sum: plain store (runs BEFORE routed atomics)
#pragma unroll
            for (int j = 0; j < 4; j++) {
                int c = d0 + wn + j * 8 + 2 * tg;
                float2 o0, o1;
                o0.x = acc[i][j][0]; o0.y = acc[i][j][1];
                o1.x = acc[i][j][2]; o1.y = acc[i][j][3];
                *(float2*)(out + (size_t)r0 * DIM + c) = o0;
                *(float2*)(out + (size_t)r1 * DIM + c) = o1;
            }
        }
    }
}

// ---------------- launcher (fork-join two-stream schedule) -----------------
extern "C" void kernel_launch(void* const* d_in, const int* in_sizes, int n_in,
                              void* d_out, int out_size) {
    static cudaStream_t s1 = nullptr;
    static cudaEvent_t evDet = nullptr, evCvt = nullptr, evGat = nullptr, evShO = nullptr;
    if (s1 == nullptr) {
        cudaFuncSetAttribute(gemm1_kernel<true>,
                             cudaFuncAttributeMaxDynamicSharedMemorySize, G1_SMEM);
        cudaFuncSetAttribute(gemm1_kernel<false>,
                             cudaFuncAttributeMaxDynamicSharedMemorySize, G1_SMEM);
        cudaFuncSetAttribute(gemm2_kernel<true>,
                             cudaFuncAttributeMaxDynamicSharedMemorySize, G2_SMEM);
        cudaFuncSetAttribute(gemm2_kernel<false>,
                             cudaFuncAttributeMaxDynamicSharedMemorySize, G2_SMEM);
        cudaStreamCreateWithFlags(&s1, cudaStreamNonBlocking);
        cudaEventCreateWithFlags(&evDet, cudaEventDisableTiming);
        cudaEventCreateWithFlags(&evCvt, cudaEventDisableTiming);
        cudaEventCreateWithFlags(&evGat, cudaEventDisableTiming);
        cudaEventCreateWithFlags(&evShO, cudaEventDisableTiming);
    }
    float* out = (float*)d_out;

    detect_kernel<<<1, 32>>>(
        (const float*)d_in[0], (const float*)d_in[1], (const float*)d_in[2],
        (const float*)d_in[3], (const float*)d_in[4], (const float*)d_in[5],
        (const float*)d_in[6], (const float*)d_in[7], (const float*)d_in[8],
        (long long)in_sizes[0], (long long)in_sizes[1], (long long)in_sizes[2],
        (long long)in_sizes[3], (long long)in_sizes[4], (long long)in_sizes[5],
        (long long)in_sizes[6], (long long)in_sizes[7], (long long)in_sizes[8]);
    cudaEventRecord(evDet, 0);

    // s1: router + gather (reads original fp32 x)
    cudaStreamWaitEvent(s1, evDet, 0);
    router_kernel<<<T_TOK / 4, dim3(32, 4), 0, s1>>>();
    gather_kernel<<<1, 1024, 0, s1>>>();
    cudaEventRecord(evGat, s1);

    // s0: fp16 conversion (x copy + weight transpose) — overlaps router+gather
    xcvt_kernel<<<T_TOK * DIM / 4 / 256, 256>>>();
    wtr_kernel<<<dim3(32, 32, 30), dim3(32, 8)>>>();
    cudaEventRecord(evCvt, 0);

    // s1: shared path: gemm1<F> then gemm2<F> writes out = shared_sum
    cudaStreamWaitEvent(s1, evCvt, 0);
    gemm1_kernel<false><<<dim3(HID / 64, T_TOK / 128, NSH), 256, G1_SMEM, s1>>>();
    gemm2_kernel<false><<<dim3(DIM / 64, T_TOK / 128, 1), 256, G2_SMEM, s1>>>(out);
    cudaEventRecord(evShO, s1);

    // s0: routed path (needs gather + cvt); final gemm2<T> atomics into out
    cudaStreamWaitEvent(0, evGat, 0);
    gemm1_kernel<true><<<dim3(HID / 64, T_TOK / 128, NE), 256, G1_SMEM>>>();
    cudaStreamWaitEvent(0, evShO, 0);
    gemm2_kernel<true><<<dim3(DIM / 64, T_TOK / 128, NE), 256, G2_SMEM>>>(out);
}